// round 4
// baseline (speedup 1.0000x reference)
#include <cuda_runtime.h>
#include <cuda_bf16.h>
#include <math.h>

// Problem constants
#define NB 32      // batch
#define CC 512     // channels
#define HH 64
#define WW 64
#define HWP 4096   // H*W
#define CB 32      // bottleneck channels
#define EPS 1e-5f

#define CH_SPLIT 8
#define CH_PER   64   // 512 / 8

// Scratch (allocation-free rule: __device__ globals)
__device__ __align__(16) float g_part[CH_SPLIT][NB * HWP];  // 4 MB partial logits
__device__ __align__(16) float g_attn[NB * HWP];            // softmax result
__device__ __align__(16) float g_ctx[NB * CC];
__device__ __align__(16) float g_v[NB][CB];                 // relu(LN(ctx@wv1^T))
__device__ int g_cnt[NB];                                    // arrive counters (self-resetting)

// ---------------------------------------------------------------------------
// K1: partial logits, channel dim split 8-ways for memory-level parallelism.
// grid = 1024 blocks (128 column-blocks x 8 chunks) x 256 threads.
// x read once -> __ldcs (evict-first). Partials kept cacheable (K2 reads them).
// ---------------------------------------------------------------------------
__global__ void k_logits(const float* __restrict__ x,
                         const float* __restrict__ wk) {
    __shared__ float swk[CH_PER];
    int chunk = blockIdx.x & 7;
    if (threadIdx.x < CH_PER) swk[threadIdx.x] = wk[chunk * CH_PER + threadIdx.x];
    __syncthreads();

    int colb = blockIdx.x >> 3;                       // 0..127
    int col  = colb * 256 + threadIdx.x;              // 0..32767 (vec4 columns)
    int n = col >> 10;
    int p = col & 1023;

    const float4* xp = reinterpret_cast<const float4*>(x)
                     + (size_t)n * CC * 1024 + (size_t)(chunk * CH_PER) * 1024 + p;
    float4 acc = make_float4(0.f, 0.f, 0.f, 0.f);

#pragma unroll 16
    for (int c = 0; c < CH_PER; c++) {
        float4 v = __ldcs(&xp[(size_t)c * 1024]);
        float w = swk[c];
        acc.x = fmaf(v.x, w, acc.x);
        acc.y = fmaf(v.y, w, acc.y);
        acc.z = fmaf(v.z, w, acc.z);
        acc.w = fmaf(v.w, w, acc.w);
    }
    reinterpret_cast<float4*>(g_part[chunk])[col] = acc;
}

// ---------------------------------------------------------------------------
// K2: sum 8 partials -> softmax over H per (n,w) column -> g_attn.
// grid = 32 (images), block = 256. Logits staged in SMEM (16 KB).
// ---------------------------------------------------------------------------
__global__ void k_softmax(void) {
    __shared__ float sl[HWP];
    int n = blockIdx.x;

    for (int i = threadIdx.x; i < 1024; i += 256) {
        float4 s = make_float4(0.f, 0.f, 0.f, 0.f);
#pragma unroll
        for (int k = 0; k < CH_SPLIT; k++) {
            float4 v = reinterpret_cast<const float4*>(g_part[k])[n * 1024 + i];
            s.x += v.x; s.y += v.y; s.z += v.z; s.w += v.w;
        }
        reinterpret_cast<float4*>(sl)[i] = s;
    }
    __syncthreads();

    if (threadIdx.x < WW) {
        int w = threadIdx.x;
        float mx = -INFINITY;
#pragma unroll
        for (int h = 0; h < HH; h++) mx = fmaxf(mx, sl[h * WW + w]);
        float s = 0.f;
#pragma unroll
        for (int h = 0; h < HH; h++) {
            float e = __expf(sl[h * WW + w] - mx);
            sl[h * WW + w] = e;
            s += e;
        }
        float inv = 1.f / s;
        float* dst = g_attn + n * HWP + w;
#pragma unroll
        for (int h = 0; h < HH; h++) dst[h * WW] = sl[h * WW + w] * inv;
    }
}

// ---------------------------------------------------------------------------
// K3: ctx[n,c] = sum_hw x*attn, one block (128 thr) per (n,c) plane.
// x loads fully front-batched (8 independent float4 LDG.128.cs per thread)
// so the DRAM queue is saturated; attn rides L2.
// Fused tail: last-arriving block per image runs GEMM1 + LN + ReLU -> g_v[n].
// ---------------------------------------------------------------------------
__global__ void k_ctx(const float* __restrict__ x,
                      const float* __restrict__ wv1,
                      const float* __restrict__ lng,
                      const float* __restrict__ lnb) {
    int nc = blockIdx.x;
    int n = nc >> 9;

    const float4* xp = reinterpret_cast<const float4*>(x) + (size_t)nc * 1024;
    const float4* ap = reinterpret_cast<const float4*>(g_attn) + (size_t)n * 1024;

    float4 xr[8];
#pragma unroll
    for (int k = 0; k < 8; k++) xr[k] = __ldcs(&xp[threadIdx.x + k * 128]);

    float s = 0.f;
#pragma unroll
    for (int k = 0; k < 8; k++) {
        float4 av = ap[threadIdx.x + k * 128];
        s = fmaf(xr[k].x, av.x, s);
        s = fmaf(xr[k].y, av.y, s);
        s = fmaf(xr[k].z, av.z, s);
        s = fmaf(xr[k].w, av.w, s);
    }
#pragma unroll
    for (int o = 16; o; o >>= 1) s += __shfl_xor_sync(0xffffffffu, s, o);

    __shared__ float red[4];
    __shared__ int is_last;
    int wid = threadIdx.x >> 5;
    int lane = threadIdx.x & 31;
    if (lane == 0) red[wid] = s;
    __syncthreads();
    if (threadIdx.x == 0) {
        g_ctx[nc] = red[0] + red[1] + red[2] + red[3];
        __threadfence();
        int old = atomicAdd(&g_cnt[n], 1);
        is_last = (old == 511);
    }
    __syncthreads();
    if (!is_last) return;

    // ---- fused MLP stage 1 for image n (128 threads) ----
    __threadfence();  // acquire: see all g_ctx writes
    __shared__ float sctx[CC];
    __shared__ float sv[CB];
    for (int i = threadIdx.x; i < CC; i += 128) sctx[i] = g_ctx[n * CC + i];
    __syncthreads();

    // 4 warps x 8 rows each: v[j] = dot(ctx, wv1[j,:])  (scalar weight loads:
    // input buffer is only 4B-aligned after the 1-float wk_b)
    for (int j = wid; j < CB; j += 4) {
        const float* wr = wv1 + j * CC;
        float p = 0.f;
#pragma unroll
        for (int k = 0; k < 16; k++) {
            int c = lane + k * 32;
            p = fmaf(__ldg(&wr[c]), sctx[c], p);
        }
#pragma unroll
        for (int o = 16; o; o >>= 1) p += __shfl_xor_sync(0xffffffffu, p, o);
        if (lane == 0) sv[j] = p;
    }
    __syncthreads();

    // warp 0: LayerNorm over 32 + ReLU -> g_v
    if (wid == 0) {
        float v = sv[lane];
        float m = v;
#pragma unroll
        for (int o = 16; o; o >>= 1) m += __shfl_xor_sync(0xffffffffu, m, o);
        float mu = m * (1.f / CB);
        float d = v - mu;
        float q = d * d;
#pragma unroll
        for (int o = 16; o; o >>= 1) q += __shfl_xor_sync(0xffffffffu, q, o);
        float var = q * (1.f / CB);
        float r = d * rsqrtf(var + EPS) * lng[lane] + lnb[lane];
        g_v[n][lane] = fmaxf(r, 0.f);
        if (lane == 0) g_cnt[n] = 0;   // reset for next graph replay
    }
}

// ---------------------------------------------------------------------------
// K5: out = x + vout broadcast. GEMM2 fused per block (2 planes).
// All 8 x loads issued FIRST (front-batched, evict-first) so DRAM latency
// overlaps the per-plane dot-product reduction; streaming stores.
// ---------------------------------------------------------------------------
__global__ void k_out(const float* __restrict__ x,
                      const float* __restrict__ wv2,
                      float* __restrict__ out) {
    __shared__ float sadd[2];
    int b = blockIdx.x;
    size_t base = (size_t)b * 2048;

    const float4* xv = reinterpret_cast<const float4*>(x);
    float4* ov = reinterpret_cast<float4*>(out);

    // front-batched loads: 8 independent LDG.128.cs in flight per thread
    float4 t[8];
#pragma unroll
    for (int i = 0; i < 8; i++) t[i] = __ldcs(&xv[base + threadIdx.x + i * 256]);

    // meanwhile: the 2 per-plane broadcast values (L2-hot operands)
    if (threadIdx.x < 64) {
        int which = threadIdx.x >> 5;
        int lane = threadIdx.x & 31;
        int nc = b * 2 + which;
        int n = nc >> 9;
        int c = nc & 511;
        float p = g_v[n][lane] * __ldg(&wv2[c * CB + lane]);   // scalar load
#pragma unroll
        for (int o = 16; o; o >>= 1) p += __shfl_xor_sync(0xffffffffu, p, o);
        if (lane == 0) sadd[which] = p;
    }
    __syncthreads();

#pragma unroll
    for (int i = 0; i < 8; i++) {
        int local = threadIdx.x + i * 256;
        float add = sadd[local >> 10];
        t[i].x += add; t[i].y += add; t[i].z += add; t[i].w += add;
        __stcs(&ov[base + local], t[i]);
    }
}

// ---------------------------------------------------------------------------
extern "C" void kernel_launch(void* const* d_in, const int* in_sizes, int n_in,
                              void* d_out, int out_size) {
    const float* x    = (const float*)d_in[0];
    const float* wk_w = (const float*)d_in[1];
    // d_in[2] = wk_b : unused (softmax shift-invariant)
    const float* wv1  = (const float*)d_in[3];
    const float* ln_g = (const float*)d_in[4];
    const float* ln_b = (const float*)d_in[5];
    const float* wv2  = (const float*)d_in[6];
    float* out = (float*)d_out;

    k_logits<<<1024, 256>>>(x, wk_w);
    k_softmax<<<NB, 256>>>();
    k_ctx<<<NB * CC, 128>>>(x, wv1, ln_g, ln_b);
    k_out<<<8192, 256>>>(x, wv2, out);
}

// round 5
// speedup vs baseline: 1.0614x; 1.0614x over previous
#include <cuda_runtime.h>
#include <cuda_bf16.h>
#include <math.h>

// Problem constants
#define NB 32      // batch
#define CC 512     // channels
#define HH 64
#define WW 64
#define HWP 4096   // H*W
#define CB 32      // bottleneck channels
#define EPS 1e-5f

#define CH_SPLIT 8
#define CH_PER   64   // 512 / 8

// Scratch (allocation-free rule: __device__ globals)
__device__ __align__(16) float g_part[CH_SPLIT][NB * HWP];  // 4 MB partial logits
__device__ __align__(16) float g_attn[NB * HWP];            // softmax result
__device__ __align__(16) float g_ctx[NB * CC];
__device__ __align__(16) float g_v[NB][CB];                 // relu(LN(ctx@wv1^T))
__device__ int g_cnt[NB];                                    // arrive counters (self-resetting)

// ---------------------------------------------------------------------------
// K1: partial logits, channel dim split 8-ways for memory-level parallelism.
// grid = 1024 blocks (128 column-blocks x 8 chunks) x 256 threads.
// DEFAULT cache policy: the ~126MB tail of x this kernel touches last stays
// L2-resident and is consumed by k_ctx (which runs in REVERSE order).
// ---------------------------------------------------------------------------
__global__ void k_logits(const float* __restrict__ x,
                         const float* __restrict__ wk) {
    __shared__ float swk[CH_PER];
    int chunk = blockIdx.x & 7;
    if (threadIdx.x < CH_PER) swk[threadIdx.x] = wk[chunk * CH_PER + threadIdx.x];
    __syncthreads();

    int colb = blockIdx.x >> 3;                       // 0..127
    int col  = colb * 256 + threadIdx.x;              // 0..32767 (vec4 columns)
    int n = col >> 10;
    int p = col & 1023;

    const float4* xp = reinterpret_cast<const float4*>(x)
                     + (size_t)n * CC * 1024 + (size_t)(chunk * CH_PER) * 1024 + p;
    float4 acc = make_float4(0.f, 0.f, 0.f, 0.f);

#pragma unroll 16
    for (int c = 0; c < CH_PER; c++) {
        float4 v = xp[(size_t)c * 1024];
        float w = swk[c];
        acc.x = fmaf(v.x, w, acc.x);
        acc.y = fmaf(v.y, w, acc.y);
        acc.z = fmaf(v.z, w, acc.z);
        acc.w = fmaf(v.w, w, acc.w);
    }
    reinterpret_cast<float4*>(g_part[chunk])[col] = acc;
}

// ---------------------------------------------------------------------------
// K2: sum 8 partials -> softmax over H per (n,w) column -> g_attn.
// grid = 32 (images), block = 256. Logits staged in SMEM (16 KB).
// ---------------------------------------------------------------------------
__global__ void k_softmax(void) {
    __shared__ float sl[HWP];
    int n = blockIdx.x;

    for (int i = threadIdx.x; i < 1024; i += 256) {
        float4 s = make_float4(0.f, 0.f, 0.f, 0.f);
#pragma unroll
        for (int k = 0; k < CH_SPLIT; k++) {
            float4 v = reinterpret_cast<const float4*>(g_part[k])[n * 1024 + i];
            s.x += v.x; s.y += v.y; s.z += v.z; s.w += v.w;
        }
        reinterpret_cast<float4*>(sl)[i] = s;
    }
    __syncthreads();

    if (threadIdx.x < WW) {
        int w = threadIdx.x;
        float mx = -INFINITY;
#pragma unroll
        for (int h = 0; h < HH; h++) mx = fmaxf(mx, sl[h * WW + w]);
        float s = 0.f;
#pragma unroll
        for (int h = 0; h < HH; h++) {
            float e = __expf(sl[h * WW + w] - mx);
            sl[h * WW + w] = e;
            s += e;
        }
        float inv = 1.f / s;
        float* dst = g_attn + n * HWP + w;
#pragma unroll
        for (int h = 0; h < HH; h++) dst[h * WW] = sl[h * WW + w] * inv;
    }
}

// ---------------------------------------------------------------------------
// K3: ctx[n,c] = sum_hw x*attn, one block (128 thr) per (n,c) plane.
// REVERSE plane order: first blocks read the x-tail that k_logits left in L2;
// the kernel finishes at the start of x, priming L2 for forward-order k_out.
// Front-batched x loads (8 independent LDG.128 in flight). Default caching.
// Fused tail: last-arriving block per image runs GEMM1 + LN + ReLU -> g_v[n].
// ---------------------------------------------------------------------------
__global__ void k_ctx(const float* __restrict__ x,
                      const float* __restrict__ wv1,
                      const float* __restrict__ lng,
                      const float* __restrict__ lnb) {
    int nc = (NB * CC - 1) - blockIdx.x;   // reverse traversal
    int n = nc >> 9;

    const float4* xp = reinterpret_cast<const float4*>(x) + (size_t)nc * 1024;
    const float4* ap = reinterpret_cast<const float4*>(g_attn) + (size_t)n * 1024;

    float4 xr[8];
#pragma unroll
    for (int k = 0; k < 8; k++) xr[k] = xp[threadIdx.x + k * 128];

    float s = 0.f;
#pragma unroll
    for (int k = 0; k < 8; k++) {
        float4 av = ap[threadIdx.x + k * 128];
        s = fmaf(xr[k].x, av.x, s);
        s = fmaf(xr[k].y, av.y, s);
        s = fmaf(xr[k].z, av.z, s);
        s = fmaf(xr[k].w, av.w, s);
    }
#pragma unroll
    for (int o = 16; o; o >>= 1) s += __shfl_xor_sync(0xffffffffu, s, o);

    __shared__ float red[4];
    __shared__ int is_last;
    int wid = threadIdx.x >> 5;
    int lane = threadIdx.x & 31;
    if (lane == 0) red[wid] = s;
    __syncthreads();
    if (threadIdx.x == 0) {
        g_ctx[nc] = red[0] + red[1] + red[2] + red[3];
        __threadfence();
        int old = atomicAdd(&g_cnt[n], 1);
        is_last = (old == 511);
    }
    __syncthreads();
    if (!is_last) return;

    // ---- fused MLP stage 1 for image n (128 threads) ----
    __threadfence();  // acquire: see all g_ctx writes
    __shared__ float sctx[CC];
    __shared__ float sv[CB];
    for (int i = threadIdx.x; i < CC; i += 128) sctx[i] = g_ctx[n * CC + i];
    __syncthreads();

    // 4 warps x 8 rows each: v[j] = dot(ctx, wv1[j,:])  (scalar weight loads:
    // input buffer is only 4B-aligned after the 1-float wk_b)
    for (int j = wid; j < CB; j += 4) {
        const float* wr = wv1 + j * CC;
        float p = 0.f;
#pragma unroll
        for (int k = 0; k < 16; k++) {
            int c = lane + k * 32;
            p = fmaf(__ldg(&wr[c]), sctx[c], p);
        }
#pragma unroll
        for (int o = 16; o; o >>= 1) p += __shfl_xor_sync(0xffffffffu, p, o);
        if (lane == 0) sv[j] = p;
    }
    __syncthreads();

    // warp 0: LayerNorm over 32 + ReLU -> g_v
    if (wid == 0) {
        float v = sv[lane];
        float m = v;
#pragma unroll
        for (int o = 16; o; o >>= 1) m += __shfl_xor_sync(0xffffffffu, m, o);
        float mu = m * (1.f / CB);
        float d = v - mu;
        float q = d * d;
#pragma unroll
        for (int o = 16; o; o >>= 1) q += __shfl_xor_sync(0xffffffffu, q, o);
        float var = q * (1.f / CB);
        float r = d * rsqrtf(var + EPS) * lng[lane] + lnb[lane];
        g_v[n][lane] = fmaxf(r, 0.f);
        if (lane == 0) g_cnt[n] = 0;   // reset for next graph replay
    }
}

// ---------------------------------------------------------------------------
// K5: out = x + vout broadcast. GEMM2 fused per block (2 planes).
// Forward order (consumes L2 residue from reverse-order k_ctx). x reads are
// last-use -> evict-first; out never re-read -> streaming stores.
// All 8 x loads front-batched to saturate the DRAM queue.
// ---------------------------------------------------------------------------
__global__ void k_out(const float* __restrict__ x,
                      const float* __restrict__ wv2,
                      float* __restrict__ out) {
    __shared__ float sadd[2];
    int b = blockIdx.x;
    size_t base = (size_t)b * 2048;

    const float4* xv = reinterpret_cast<const float4*>(x);
    float4* ov = reinterpret_cast<float4*>(out);

    float4 t[8];
#pragma unroll
    for (int i = 0; i < 8; i++) t[i] = __ldcs(&xv[base + threadIdx.x + i * 256]);

    if (threadIdx.x < 64) {
        int which = threadIdx.x >> 5;
        int lane = threadIdx.x & 31;
        int nc = b * 2 + which;
        int n = nc >> 9;
        int c = nc & 511;
        float p = g_v[n][lane] * __ldg(&wv2[c * CB + lane]);   // scalar load
#pragma unroll
        for (int o = 16; o; o >>= 1) p += __shfl_xor_sync(0xffffffffu, p, o);
        if (lane == 0) sadd[which] = p;
    }
    __syncthreads();

#pragma unroll
    for (int i = 0; i < 8; i++) {
        int local = threadIdx.x + i * 256;
        float add = sadd[local >> 10];
        t[i].x += add; t[i].y += add; t[i].z += add; t[i].w += add;
        __stcs(&ov[base + local], t[i]);
    }
}

// ---------------------------------------------------------------------------
extern "C" void kernel_launch(void* const* d_in, const int* in_sizes, int n_in,
                              void* d_out, int out_size) {
    const float* x    = (const float*)d_in[0];
    const float* wk_w = (const float*)d_in[1];
    // d_in[2] = wk_b : unused (softmax shift-invariant)
    const float* wv1  = (const float*)d_in[3];
    const float* ln_g = (const float*)d_in[4];
    const float* ln_b = (const float*)d_in[5];
    const float* wv2  = (const float*)d_in[6];
    float* out = (float*)d_out;

    k_logits<<<1024, 256>>>(x, wk_w);
    k_softmax<<<NB, 256>>>();
    k_ctx<<<NB * CC, 128>>>(x, wv1, ln_g, ln_b);
    k_out<<<8192, 256>>>(x, wv2, out);
}